// round 12
// baseline (speedup 1.0000x reference)
#include <cuda_runtime.h>
#include <math_constants.h>
#include <math.h>

#define NA 1344
#define NW 42   // 1344/32
#define QCAP 5120

// Non-contractible fp32 ops (match XLA's no-FMA elementwise lowering)
__device__ __forceinline__ float fa(float a, float b) { return __fadd_rn(a, b); }
__device__ __forceinline__ float fs(float a, float b) { return __fsub_rn(a, b); }
__device__ __forceinline__ float fm(float a, float b) { return __fmul_rn(a, b); }
__device__ __forceinline__ float fd(float a, float b) { return __fdiv_rn(a, b); }

// ---------------- device scratch (no allocations allowed) ----------------
__device__ float g_conf[NA], g_cls0[NA], g_cls1[NA], g_x[NA], g_y[NA];
__device__ float g_rect[NA * 8];
__device__ float g_cor[NA * 8];
__device__ float g_a5[NA];
__device__ float g_ab[NA * 4];   // min0, max0, min1, max1 of corners
__device__ unsigned char g_mask[NA];
__device__ unsigned int  g_Sc[NA * NW];   // suppression bits, RANK space, stride NWc
__device__ int           g_order[NA];     // rank -> anchor
__device__ int           g_rank[NA];      // anchor -> rank
__device__ unsigned char g_keep[NA];
__device__ int           g_nmask;

// ---------------- kernel A: decode + geometry per anchor ----------------
__global__ void k_geom(const float* __restrict__ out3, const float* __restrict__ out4,
                       const float* __restrict__ out5,
                       const float* __restrict__ o13, const float* __restrict__ o14,
                       const float* __restrict__ o15,
                       const float* __restrict__ of3, const float* __restrict__ of4,
                       const float* __restrict__ of5)
{
    int t = blockIdx.x * blockDim.x + threadIdx.x;
    if (t == 0) { g_nmask = 0; }
    if (t >= NA) return;
    const float *out, *o1, *off;
    int hw, w, r;
    float stride;
    if (t < 1024)      { out = out3; o1 = o13; off = of3; hw = 1024; w = 32; stride = 4.f;  r = t; }
    else if (t < 1280) { out = out4; o1 = o14; off = of4; hw = 256;  w = 16; stride = 8.f;  r = t - 1024; }
    else               { out = out5; o1 = o15; off = of5; hw = 64;   w = 8;  stride = 16.f; r = t - 1280; }
    int row = r / w, col = r - row * w;

    float conf = out[r];
    float c0 = out[hw + r];
    float c1 = out[2 * hw + r];
    float x = fa(fm(out[3 * hw + r], stride), fm(stride, (float)col));
    float y = fa(fm(out[4 * hw + r], stride), fm(stride, (float)row));

    float F[18];
#pragma unroll
    for (int c = 0; c < 18; c++)
        F[c] = fa(fa(off[c * hw + r], o1[c * hw + r]), ((c & 1) ? x : y));

    float xmn = F[1], xmx = F[1], ymn = F[0], ymx = F[0];
#pragma unroll
    for (int k = 1; k < 9; k++) {
        xmn = fminf(xmn, F[2 * k + 1]); xmx = fmaxf(xmx, F[2 * k + 1]);
        ymn = fminf(ymn, F[2 * k]);     ymx = fmaxf(ymx, F[2 * k]);
    }
    float area = fd(fm(fs(xmx, xmn), fs(ymx, ymn)), 40.0f);
    float sig = fd(1.0f, fa(1.0f, expf(-area)));
    bool cm = conf > fm(0.7f, sig);

    float P0[9], P1[9];
#pragma unroll
    for (int k = 0; k < 9; k++) { P0[k] = F[2 * k]; P1[k] = F[2 * k + 1]; }
    float bestA = CUDART_INF_F;
    float bc = 1.f, bs = 0.f, bu0 = 0.f, bu1 = 0.f, bv0 = 0.f, bv1 = 0.f;
    for (int pi = 0; pi < 8; pi++) {
        for (int pj = pi + 1; pj < 9; pj++) {
            float d0 = fs(P0[pj], P0[pi]), d1 = fs(P1[pj], P1[pi]);
            float nrm = sqrtf(fa(fa(fm(d0, d0), fm(d1, d1)), 1e-12f));
            float cc = fd(d0, nrm), ss = fd(d1, nrm);
            float u0 = fa(fm(P0[0], cc), fm(P1[0], ss));
            float v0 = fa(fm(-P0[0], ss), fm(P1[0], cc));
            float umn = u0, umx = u0, vmn = v0, vmx = v0;
#pragma unroll
            for (int k = 1; k < 9; k++) {
                float u = fa(fm(P0[k], cc), fm(P1[k], ss));
                float v = fa(fm(-P0[k], ss), fm(P1[k], cc));
                umn = fminf(umn, u); umx = fmaxf(umx, u);
                vmn = fminf(vmn, v); vmx = fmaxf(vmx, v);
            }
            float ar = fm(fs(umx, umn), fs(vmx, vmn));
            if (ar < bestA) { bestA = ar; bc = cc; bs = ss; bu0 = umn; bu1 = umx; bv0 = vmn; bv1 = vmx; }
        }
    }
    float cu[4] = {bu0, bu1, bu1, bu0};
    float cv[4] = {bv0, bv0, bv1, bv1};
    float R[8];
#pragma unroll
    for (int q = 0; q < 4; q++) {
        R[2 * q]     = fs(fm(cu[q], bc), fm(cv[q], bs));
        R[2 * q + 1] = fa(fm(cu[q], bs), fm(cv[q], bc));
    }
    float dw0 = fs(R[0], R[2]), dw1 = fs(R[1], R[3]);
    float wb = sqrtf(fa(fm(dw0, dw0), fm(dw1, dw1)));
    float dh0 = fs(R[4], R[2]), dh1 = fs(R[5], R[3]);
    float hb = sqrtf(fa(fm(dh0, dh0), fm(dh1, dh1)));
    float cxb = fm(fa(fa(fa(R[1], R[3]), R[5]), R[7]), 0.25f);
    float cyb = fm(fa(fa(fa(R[0], R[2]), R[4]), R[6]), 0.25f);
    float ang = atan2f(fd(fs(R[0], R[2]), fs(R[1], R[3])), 1.0f);
    float cs = cosf(ang), sn = sinf(ang);
    const float LX[4] = {-0.5f, 0.5f, 0.5f, -0.5f};
    const float LY[4] = {-0.5f, -0.5f, 0.5f, 0.5f};
    float C[8];
#pragma unroll
    for (int q = 0; q < 4; q++) {
        float lx = fm(LX[q], wb), ly = fm(LY[q], hb);
        C[2 * q]     = fs(fa(cxb, fm(lx, cs)), fm(ly, sn));
        C[2 * q + 1] = fa(fa(cyb, fm(lx, sn)), fm(ly, cs));
    }
    float m0 = fminf(fminf(C[0], C[2]), fminf(C[4], C[6]));
    float M0 = fmaxf(fmaxf(C[0], C[2]), fmaxf(C[4], C[6]));
    float m1 = fminf(fminf(C[1], C[3]), fminf(C[5], C[7]));
    float M1 = fmaxf(fmaxf(C[1], C[3]), fmaxf(C[5], C[7]));

    g_conf[t] = conf; g_cls0[t] = c0; g_cls1[t] = c1;
    g_x[t] = x; g_y[t] = y;
    g_mask[t] = cm ? 1 : 0;
#pragma unroll
    for (int k = 0; k < 8; k++) { g_rect[t * 8 + k] = R[k]; g_cor[t * 8 + k] = C[k]; }
    g_a5[t] = fm(wb, hb);
    g_ab[t * 4 + 0] = m0; g_ab[t * 4 + 1] = M0;
    g_ab[t * 4 + 2] = m1; g_ab[t * 4 + 3] = M1;
}

// ---------------- kernel: stable descending rank + zero scratch ----------------
__global__ void k_rank()
{
    __shared__ float key[NA];
    for (int i = threadIdx.x; i < NA; i += blockDim.x)
        key[i] = g_mask[i] ? g_conf[i] : -CUDART_INF_F;
    __syncthreads();
    int gt = blockIdx.x * blockDim.x + threadIdx.x;
    int nthr = gridDim.x * blockDim.x;
    for (int idx = gt; idx < NA * NW; idx += nthr) g_Sc[idx] = 0u;
    for (int idx = gt; idx < NA; idx += nthr) g_keep[idx] = 0;
    int i = gt;
    if (i >= NA) return;
    float ki = key[i];
    int rk = 0;
    for (int j = 0; j < NA; j++) {
        float kj = key[j];
        rk += ((kj > ki) || (kj == ki && j > i)) ? 1 : 0;
    }
    g_order[rk] = i;
    g_rank[i] = rk;
    if (g_mask[i]) atomicAdd(&g_nmask, 1);
}

// ---------------- val/n only (first phase, bit-faithful) ----------------
__device__ __forceinline__ int quad_val_n(const float* __restrict__ A, const float* __restrict__ B)
{
    float A0[4], A1[4], B0[4], B1[4];
#pragma unroll
    for (int q = 0; q < 4; q++) {
        A0[q] = A[2 * q]; A1[q] = A[2 * q + 1];
        B0[q] = B[2 * q]; B1[q] = B[2 * q + 1];
    }
    unsigned val = 0;
#pragma unroll
    for (int p = 0; p < 4; p++) {
        bool pos = true, neg = true;
#pragma unroll
        for (int e = 0; e < 4; e++) {
            int e1 = (e + 1) & 3;
            float E0 = fs(A0[e1], A0[e]), E1 = fs(A1[e1], A1[e]);
            float r0 = fs(B0[p], A0[e]), r1 = fs(B1[p], A1[e]);
            float cr = fs(fm(E0, r1), fm(E1, r0));
            pos = pos && (cr >= 0.f);
            neg = neg && (cr <= 0.f);
        }
        if (pos || neg) val |= 1u << (4 + p);
    }
#pragma unroll
    for (int p = 0; p < 4; p++) {
        bool pos = true, neg = true;
#pragma unroll
        for (int e = 0; e < 4; e++) {
            int e1 = (e + 1) & 3;
            float E0 = fs(B0[e1], B0[e]), E1 = fs(B1[e1], B1[e]);
            float r0 = fs(A0[p], B0[e]), r1 = fs(A1[p], B1[e]);
            float cr = fs(fm(E0, r1), fm(E1, r0));
            pos = pos && (cr >= 0.f);
            neg = neg && (cr <= 0.f);
        }
        if (pos || neg) val |= 1u << p;
    }
#pragma unroll
    for (int a = 0; a < 4; a++) {
        int a1 = (a + 1) & 3;
        float rA0 = fs(A0[a1], A0[a]), rA1 = fs(A1[a1], A1[a]);
#pragma unroll
        for (int b = 0; b < 4; b++) {
            int b1 = (b + 1) & 3;
            float rB0 = fs(B0[b1], B0[b]), rB1 = fs(B1[b1], B1[b]);
            float qp0 = fs(B0[b], A0[a]), qp1 = fs(B1[b], A1[a]);
            float den = fs(fm(rA0, rB1), fm(rA1, rB0));
            float dsafe = (fabsf(den) < 1e-9f) ? 1e-9f : den;
            float tt = fd(fs(fm(qp0, rB1), fm(qp1, rB0)), dsafe);
            float uu = fd(fs(fm(qp0, rA1), fm(qp1, rA0)), dsafe);
            bool ok = (fabsf(den) > 1e-9f) && (tt >= 0.f) && (tt <= 1.f) && (uu >= 0.f) && (uu <= 1.f);
            if (ok) val |= 1u << (8 + a * 4 + b);
        }
    }
    return __popc(val);
}

// ---------------- convex quad intersection area (fp32, bit-faithful) ----------------
// Requires all 32 lanes of the warp converged (uses full-mask shuffles).
__device__ __forceinline__ float quad_inter_area(const float* __restrict__ A, const float* __restrict__ B)
{
    float A0[4], A1[4], B0[4], B1[4];
#pragma unroll
    for (int q = 0; q < 4; q++) {
        A0[q] = A[2 * q]; A1[q] = A[2 * q + 1];
        B0[q] = B[2 * q]; B1[q] = B[2 * q + 1];
    }
    bool inA[4], inB[4];
#pragma unroll
    for (int p = 0; p < 4; p++) {
        bool pos = true, neg = true;
#pragma unroll
        for (int e = 0; e < 4; e++) {
            int e1 = (e + 1) & 3;
            float E0 = fs(A0[e1], A0[e]), E1 = fs(A1[e1], A1[e]);
            float r0 = fs(B0[p], A0[e]), r1 = fs(B1[p], A1[e]);
            float cr = fs(fm(E0, r1), fm(E1, r0));
            pos = pos && (cr >= 0.f);
            neg = neg && (cr <= 0.f);
        }
        inA[p] = pos || neg;
    }
#pragma unroll
    for (int p = 0; p < 4; p++) {
        bool pos = true, neg = true;
#pragma unroll
        for (int e = 0; e < 4; e++) {
            int e1 = (e + 1) & 3;
            float E0 = fs(B0[e1], B0[e]), E1 = fs(B1[e1], B1[e]);
            float r0 = fs(A0[p], B0[e]), r1 = fs(A1[p], B1[e]);
            float cr = fs(fm(E0, r1), fm(E1, r0));
            pos = pos && (cr >= 0.f);
            neg = neg && (cr <= 0.f);
        }
        inB[p] = pos || neg;
    }
    float Px[24], Py[24];
    unsigned val = 0;
#pragma unroll
    for (int p = 0; p < 4; p++) {
        Px[p] = A0[p]; Py[p] = A1[p];
        if (inB[p]) val |= 1u << p;
        Px[4 + p] = B0[p]; Py[4 + p] = B1[p];
        if (inA[p]) val |= 1u << (4 + p);
    }
#pragma unroll
    for (int a = 0; a < 4; a++) {
        int a1 = (a + 1) & 3;
        float rA0 = fs(A0[a1], A0[a]), rA1 = fs(A1[a1], A1[a]);
#pragma unroll
        for (int b = 0; b < 4; b++) {
            int b1 = (b + 1) & 3;
            float rB0 = fs(B0[b1], B0[b]), rB1 = fs(B1[b1], B1[b]);
            float qp0 = fs(B0[b], A0[a]), qp1 = fs(B1[b], A1[a]);
            float den = fs(fm(rA0, rB1), fm(rA1, rB0));
            float dsafe = (fabsf(den) < 1e-9f) ? 1e-9f : den;
            float tt = fd(fs(fm(qp0, rB1), fm(qp1, rB0)), dsafe);
            float uu = fd(fs(fm(qp0, rA1), fm(qp1, rA0)), dsafe);
            bool ok = (fabsf(den) > 1e-9f) && (tt >= 0.f) && (tt <= 1.f) && (uu >= 0.f) && (uu <= 1.f);
            int id = 8 + a * 4 + b;
            Px[id] = fa(A0[a], fm(tt, rA0));
            Py[id] = fa(A1[a], fm(tt, rA1));
            if (ok) val |= 1u << id;
        }
    }
    int n = __popc(val);
    float sx = 0.f, sy = 0.f;
#pragma unroll
    for (int t = 0; t < 24; t++) {
        bool v = (val >> t) & 1u;
        sx = fa(sx, v ? Px[t] : 0.0f);
        sy = fa(sy, v ? Py[t] : 0.0f);
    }
    float inv = (float)max(n, 1);
    float cx = fd(sx, inv), cy = fd(sy, inv);
    float ang[24];
#pragma unroll
    for (int t = 0; t < 24; t++) {
        Px[t] = fs(Px[t], cx); Py[t] = fs(Py[t], cy);
        ang[t] = ((val >> t) & 1u) ? atan2f(Py[t], Px[t]) : 1e9f;
    }
    int rk[24];
#pragma unroll
    for (int t = 0; t < 24; t++) rk[t] = 0;
#pragma unroll
    for (int t = 0; t < 24; t++) {
#pragma unroll
        for (int u = t + 1; u < 24; u++) {
            bool u_first = (ang[u] < ang[t]);
            rk[t] += u_first ? 1 : 0;
            rk[u] += u_first ? 0 : 1;
        }
    }
    float xo0 = 0.f, yo0 = 0.f;
#pragma unroll
    for (int t = 0; t < 24; t++) {
        bool is0 = (rk[t] == 0);
        xo0 = is0 ? Px[t] : xo0;
        yo0 = is0 ? Py[t] : yo0;
    }
    int nmax = n;
#pragma unroll
    for (int o = 16; o; o >>= 1) nmax = max(nmax, __shfl_xor_sync(0xffffffffu, nmax, o));
    float ssum = 0.f;
    float pxc = xo0, pyc = yo0;
    for (int pos = 1; pos < nmax; pos++) {
        float nx = 0.f, ny = 0.f;
#pragma unroll
        for (int t = 0; t < 24; t++) {
            bool h = (rk[t] == pos);
            nx = h ? Px[t] : nx;
            ny = h ? Py[t] : ny;
        }
        if (pos < n) {
            ssum = fa(ssum, fs(fm(pxc, ny), fm(pyc, nx)));
            pxc = nx; pyc = ny;
        }
    }
    ssum = fa(ssum, fs(fm(pxc, yo0), fm(pyc, xo0)));
    float aout = fm(0.5f, fabsf(ssum));
    return (n >= 3) ? aout : 0.f;
}

// ---------------- fused kernel B: cheap pass + in-block filter + heavy ----------------
__global__ void __launch_bounds__(256) k_ph()
{
    __shared__ unsigned sq[QCAP];    // AABB-overlap candidates
    __shared__ unsigned sq2[QCAP];   // n>=3 survivors
    __shared__ int sqn, sqn2;
    int tid = threadIdx.x;
    int nmask = g_nmask;
    int NWc = (nmask + 31) >> 5;

    if (tid == 0) { sqn = 0; sqn2 = 0; }
    __syncthreads();

    auto flush = [&]() {
        __syncthreads();
        int nq = sqn;
        // B1: exact n>=3 filter (n<3 => reference area exactly 0 => bit 0)
        for (int idx = tid; idx < nq; idx += 256) {
            unsigned pk = sq[idx];
            int i = pk >> 16, j = pk & 0xFFFF;
            int n = quad_val_n(&g_cor[i * 8], &g_cor[j * 8]);
            if (n >= 3) {
                int q = atomicAdd(&sqn2, 1);
                sq2[q] = pk;
            }
        }
        __syncthreads();
        int nq2 = sqn2;
        // B2: full hull on survivors, live-padded so warps stay converged
        for (int base = 0; base < nq2; base += 256) {
            int idx = base + tid;
            bool live = idx < nq2;
            unsigned pk = sq2[live ? idx : 0];
            int i = pk >> 16, j = pk & 0xFFFF;
            float inter = quad_inter_area(&g_cor[i * 8], &g_cor[j * 8]);
            float iou = fd(inter, fa(fs(fa(g_a5[i], g_a5[j]), inter), 1e-9f));
            if (live && iou >= 0.2f) {
                int ri = g_rank[i], rj = g_rank[j];
                atomicOr(&g_Sc[ri * NWc + (rj >> 5)], 1u << (rj & 31));
            }
        }
        __syncthreads();
        if (tid == 0) { sqn = 0; sqn2 = 0; }
        __syncthreads();
    };

    for (int i = blockIdx.x; i < NA; i += gridDim.x) {
        if (!g_mask[i]) continue;           // uniform per block
        int ri = g_rank[i];
        float Q[8];
#pragma unroll
        for (int k = 0; k < 8; k++) Q[k] = g_rect[i * 8 + k];
        float im0 = g_ab[i * 4 + 0], iM0 = g_ab[i * 4 + 1];
        float im1 = g_ab[i * 4 + 2], iM1 = g_ab[i * 4 + 3];

        for (int j = tid; j < NA; j += 256) {
            int rj = g_rank[j];
            if (rj >= nmask) continue;      // column never read by the scan
            float p0 = g_y[j], p1 = g_x[j];
            bool pos = true, neg = true;
#pragma unroll
            for (int e = 0; e < 4; e++) {
                int e1 = (e + 1) & 3;
                float E0 = fs(Q[2 * e1], Q[2 * e]), E1 = fs(Q[2 * e1 + 1], Q[2 * e + 1]);
                float r0 = fs(p0, Q[2 * e]), r1 = fs(p1, Q[2 * e + 1]);
                float cr = fs(fm(E0, r1), fm(E1, r0));
                pos = pos && (cr >= 0.f);
                neg = neg && (cr <= 0.f);
            }
            bool bit = pos || neg;
            if (bit) {
                atomicOr(&g_Sc[ri * NWc + (rj >> 5)], 1u << (rj & 31));
                continue;
            }
            float jm0 = g_ab[j * 4 + 0], jM0 = g_ab[j * 4 + 1];
            float jm1 = g_ab[j * 4 + 2], jM1 = g_ab[j * 4 + 3];
            bool ov = !(iM0 < jm0 || jM0 < im0 || iM1 < jm1 || jM1 < im1);
            if (ov) {
                int q = atomicAdd(&sqn, 1);
                sq[q] = ((unsigned)i << 16) | (unsigned)j;
            }
        }
        // flush before the queue can overflow on the next row (<= NA adds per row)
        __syncthreads();
        if (sqn > QCAP - NA) flush();
    }
    flush();
}

// ---------------- kernel C: warp-chunked sequential NMS + outputs (R9 exact) ----------------
__global__ void __launch_bounds__(1024) k_nms(float* __restrict__ dout)
{
    extern __shared__ unsigned int sS[];
    __shared__ int sc0, sc1;
    int tid = threadIdx.x;

    int nmask = g_nmask;
    int nchunks = (nmask + 31) >> 5;
    int NWc = nchunks;
    int nrows = nchunks << 5;
    int* sOrd = (int*)(sS + nrows * NWc);

    for (int idx = tid; idx < nrows * NWc; idx += blockDim.x) sS[idx] = g_Sc[idx];
    for (int idx = tid; idx < nrows; idx += blockDim.x) sOrd[idx] = g_order[idx];
    if (tid == 0) { sc0 = 0; sc1 = 0; }
    __syncthreads();

    if (tid < 32) {
        int lane = tid;
        auto initw = [&](int w) -> unsigned {
            int base = w << 5;
            if (base + 32 <= nmask) return 0u;
            if (base >= nmask) return 0xFFFFFFFFu;
            return 0xFFFFFFFFu << (nmask - base);
        };
        unsigned sup0 = initw(lane);
        unsigned sup1 = initw(32 + lane);
        bool lo = lane < NWc;
        bool hi = (32 + lane) < NWc;

        for (int k = 0; k < nmask; k += 32) {
            int c = k >> 5;
            unsigned vsel = (c < 32) ? sup0 : sup1;
            unsigned sup32 = __shfl_sync(0xffffffffu, vsel, c & 31);
            unsigned mw[32];
#pragma unroll
            for (int b = 0; b < 32; b++) mw[b] = sS[(k + b) * NWc + c];
            unsigned chk = 0;
#pragma unroll
            for (int b = 0; b < 32; b++) chk ^= mw[b];
            unsigned s32 = sup32;
            asm volatile("" : "+r"(s32) : "r"(chk));
            unsigned act = 0;
#pragma unroll
            for (int b = 0; b < 32; b++) {
                unsigned m = (unsigned)(((int)(s32 << (31 - b))) >> 31);
                act |= (~m) & (1u << b);
                s32 |= mw[b] & ~m;
            }
            if ((act >> lane) & 1u) g_keep[sOrd[k + lane]] = 1;
            unsigned acc0 = 0u, acc1 = 0u;
#pragma unroll
            for (int b = 0; b < 32; b++) {
                unsigned sel = 0u - ((act >> b) & 1u);
                unsigned w0 = lo ? sS[(k + b) * NWc + lane] : 0u;
                acc0 |= w0 & sel;
                unsigned w1 = hi ? sS[(k + b) * NWc + 32 + lane] : 0u;
                acc1 |= w1 & sel;
            }
            sup0 |= acc0;
            sup1 |= acc1;
        }
    }
    __syncthreads();

    int l0 = 0, l1 = 0;
    for (int i = tid; i < NA; i += blockDim.x) {
        if (g_keep[i]) {
            float mx = fmaxf(g_cls0[i], g_cls1[i]);
            if (g_cls0[i] == mx) l0++;
            if (g_cls1[i] == mx) l1++;
        }
    }
    atomicAdd(&sc0, l0);
    atomicAdd(&sc1, l1);
    __syncthreads();
    if (tid == 0) { dout[0] = (float)sc0; dout[1] = (float)sc1; }

    for (int t = tid; t < NA; t += blockDim.x) {
        bool kp = g_keep[t] != 0;
        float mx = fmaxf(g_cls0[t], g_cls1[t]);
        bool m0 = kp && (g_cls0[t] == mx);
        bool m1 = kp && (g_cls1[t] == mx);
        float x = g_x[t], y = g_y[t];
        float* res = dout + 2;
        res[0 * NA * 2 + t * 2 + 0] = m0 ? x : 0.f;
        res[0 * NA * 2 + t * 2 + 1] = m0 ? y : 0.f;
        res[1 * NA * 2 + t * 2 + 0] = m1 ? x : 0.f;
        res[1 * NA * 2 + t * 2 + 1] = m1 ? y : 0.f;
        float* ro = dout + 2 + 2 * NA * 2;
        float kf = kp ? 1.f : 0.f;
#pragma unroll
        for (int k = 0; k < 8; k++)
            ro[t * 8 + k] = fm(g_rect[t * 8 + k], kf);
    }
}

// ---------------- launcher ----------------
extern "C" void kernel_launch(void* const* d_in, const int* in_sizes, int n_in,
                              void* d_out, int out_size)
{
    const float* out3 = (const float*)d_in[0];
    const float* out4 = (const float*)d_in[1];
    const float* out5 = (const float*)d_in[2];
    const float* o13  = (const float*)d_in[3];
    const float* o14  = (const float*)d_in[4];
    const float* o15  = (const float*)d_in[5];
    const float* of3  = (const float*)d_in[6];
    const float* of4  = (const float*)d_in[7];
    const float* of5  = (const float*)d_in[8];
    float* dout = (float*)d_out;

    k_geom<<<(NA + 127) / 128, 128>>>(out3, out4, out5, o13, o14, o15, of3, of4, of5);
    k_rank<<<(NA + 255) / 256, 256>>>();
    k_ph<<<296, 256>>>();
    size_t sh = (size_t)NA * NW * sizeof(unsigned int) + (size_t)NA * sizeof(int);  // worst case
    cudaFuncSetAttribute(k_nms, cudaFuncAttributeMaxDynamicSharedMemorySize, (int)sh);
    k_nms<<<1, 1024, sh>>>(dout);
}

// round 13
// speedup vs baseline: 1.1138x; 1.1138x over previous
#include <cuda_runtime.h>
#include <math_constants.h>
#include <math.h>

#define NA 1344
#define NW 42   // 1344/32

// Non-contractible fp32 ops (match XLA's no-FMA elementwise lowering)
__device__ __forceinline__ float fa(float a, float b) { return __fadd_rn(a, b); }
__device__ __forceinline__ float fs(float a, float b) { return __fsub_rn(a, b); }
__device__ __forceinline__ float fm(float a, float b) { return __fmul_rn(a, b); }
__device__ __forceinline__ float fd(float a, float b) { return __fdiv_rn(a, b); }

// ---------------- device scratch (no allocations allowed) ----------------
__device__ float g_conf[NA], g_cls0[NA], g_cls1[NA], g_x[NA], g_y[NA];
__device__ float g_rect[NA * 8];
__device__ float g_cor[NA * 8];
__device__ float g_a5[NA];
__device__ float g_ab[NA * 4];   // min0, max0, min1, max1 of corners
__device__ unsigned char g_mask[NA];
__device__ unsigned int  g_Sc[NA * NW];   // suppression bits, RANK space, stride NWc
__device__ int           g_order[NA];     // rank -> anchor
__device__ int           g_rank[NA];      // anchor -> rank
__device__ unsigned char g_keep[NA];
__device__ int           g_nmask;
__device__ int           g_nheavy;
__device__ unsigned int  g_hq[NA * NA];   // heavy pair queue (i<<16 | j)

// ---------------- kernel A: decode + geometry per anchor ----------------
__global__ void k_geom(const float* __restrict__ out3, const float* __restrict__ out4,
                       const float* __restrict__ out5,
                       const float* __restrict__ o13, const float* __restrict__ o14,
                       const float* __restrict__ o15,
                       const float* __restrict__ of3, const float* __restrict__ of4,
                       const float* __restrict__ of5)
{
    int t = blockIdx.x * blockDim.x + threadIdx.x;
    if (t == 0) { g_nmask = 0; g_nheavy = 0; }
    if (t >= NA) return;
    const float *out, *o1, *off;
    int hw, w, r;
    float stride;
    if (t < 1024)      { out = out3; o1 = o13; off = of3; hw = 1024; w = 32; stride = 4.f;  r = t; }
    else if (t < 1280) { out = out4; o1 = o14; off = of4; hw = 256;  w = 16; stride = 8.f;  r = t - 1024; }
    else               { out = out5; o1 = o15; off = of5; hw = 64;   w = 8;  stride = 16.f; r = t - 1280; }
    int row = r / w, col = r - row * w;

    float conf = out[r];
    float c0 = out[hw + r];
    float c1 = out[2 * hw + r];
    float x = fa(fm(out[3 * hw + r], stride), fm(stride, (float)col));
    float y = fa(fm(out[4 * hw + r], stride), fm(stride, (float)row));

    float F[18];
#pragma unroll
    for (int c = 0; c < 18; c++)
        F[c] = fa(fa(off[c * hw + r], o1[c * hw + r]), ((c & 1) ? x : y));

    float xmn = F[1], xmx = F[1], ymn = F[0], ymx = F[0];
#pragma unroll
    for (int k = 1; k < 9; k++) {
        xmn = fminf(xmn, F[2 * k + 1]); xmx = fmaxf(xmx, F[2 * k + 1]);
        ymn = fminf(ymn, F[2 * k]);     ymx = fmaxf(ymx, F[2 * k]);
    }
    float area = fd(fm(fs(xmx, xmn), fs(ymx, ymn)), 40.0f);
    float sig = fd(1.0f, fa(1.0f, expf(-area)));
    bool cm = conf > fm(0.7f, sig);

    float P0[9], P1[9];
#pragma unroll
    for (int k = 0; k < 9; k++) { P0[k] = F[2 * k]; P1[k] = F[2 * k + 1]; }
    float bestA = CUDART_INF_F;
    float bc = 1.f, bs = 0.f, bu0 = 0.f, bu1 = 0.f, bv0 = 0.f, bv1 = 0.f;
    for (int pi = 0; pi < 8; pi++) {
        for (int pj = pi + 1; pj < 9; pj++) {
            float d0 = fs(P0[pj], P0[pi]), d1 = fs(P1[pj], P1[pi]);
            float nrm = sqrtf(fa(fa(fm(d0, d0), fm(d1, d1)), 1e-12f));
            float cc = fd(d0, nrm), ss = fd(d1, nrm);
            float u0 = fa(fm(P0[0], cc), fm(P1[0], ss));
            float v0 = fa(fm(-P0[0], ss), fm(P1[0], cc));
            float umn = u0, umx = u0, vmn = v0, vmx = v0;
#pragma unroll
            for (int k = 1; k < 9; k++) {
                float u = fa(fm(P0[k], cc), fm(P1[k], ss));
                float v = fa(fm(-P0[k], ss), fm(P1[k], cc));
                umn = fminf(umn, u); umx = fmaxf(umx, u);
                vmn = fminf(vmn, v); vmx = fmaxf(vmx, v);
            }
            float ar = fm(fs(umx, umn), fs(vmx, vmn));
            if (ar < bestA) { bestA = ar; bc = cc; bs = ss; bu0 = umn; bu1 = umx; bv0 = vmn; bv1 = vmx; }
        }
    }
    float cu[4] = {bu0, bu1, bu1, bu0};
    float cv[4] = {bv0, bv0, bv1, bv1};
    float R[8];
#pragma unroll
    for (int q = 0; q < 4; q++) {
        R[2 * q]     = fs(fm(cu[q], bc), fm(cv[q], bs));
        R[2 * q + 1] = fa(fm(cu[q], bs), fm(cv[q], bc));
    }
    float dw0 = fs(R[0], R[2]), dw1 = fs(R[1], R[3]);
    float wb = sqrtf(fa(fm(dw0, dw0), fm(dw1, dw1)));
    float dh0 = fs(R[4], R[2]), dh1 = fs(R[5], R[3]);
    float hb = sqrtf(fa(fm(dh0, dh0), fm(dh1, dh1)));
    float cxb = fm(fa(fa(fa(R[1], R[3]), R[5]), R[7]), 0.25f);
    float cyb = fm(fa(fa(fa(R[0], R[2]), R[4]), R[6]), 0.25f);
    float ang = atan2f(fd(fs(R[0], R[2]), fs(R[1], R[3])), 1.0f);
    float cs = cosf(ang), sn = sinf(ang);
    const float LX[4] = {-0.5f, 0.5f, 0.5f, -0.5f};
    const float LY[4] = {-0.5f, -0.5f, 0.5f, 0.5f};
    float C[8];
#pragma unroll
    for (int q = 0; q < 4; q++) {
        float lx = fm(LX[q], wb), ly = fm(LY[q], hb);
        C[2 * q]     = fs(fa(cxb, fm(lx, cs)), fm(ly, sn));
        C[2 * q + 1] = fa(fa(cyb, fm(lx, sn)), fm(ly, cs));
    }
    float m0 = fminf(fminf(C[0], C[2]), fminf(C[4], C[6]));
    float M0 = fmaxf(fmaxf(C[0], C[2]), fmaxf(C[4], C[6]));
    float m1 = fminf(fminf(C[1], C[3]), fminf(C[5], C[7]));
    float M1 = fmaxf(fmaxf(C[1], C[3]), fmaxf(C[5], C[7]));

    g_conf[t] = conf; g_cls0[t] = c0; g_cls1[t] = c1;
    g_x[t] = x; g_y[t] = y;
    g_mask[t] = cm ? 1 : 0;
#pragma unroll
    for (int k = 0; k < 8; k++) { g_rect[t * 8 + k] = R[k]; g_cor[t * 8 + k] = C[k]; }
    g_a5[t] = fm(wb, hb);
    g_ab[t * 4 + 0] = m0; g_ab[t * 4 + 1] = M0;
    g_ab[t * 4 + 2] = m1; g_ab[t * 4 + 3] = M1;
}

// ---------------- kernel: stable descending rank + zero scratch ----------------
__global__ void k_rank()
{
    __shared__ float key[NA];
    for (int i = threadIdx.x; i < NA; i += blockDim.x)
        key[i] = g_mask[i] ? g_conf[i] : -CUDART_INF_F;
    __syncthreads();
    int gt = blockIdx.x * blockDim.x + threadIdx.x;
    int nthr = gridDim.x * blockDim.x;
    for (int idx = gt; idx < NA * NW; idx += nthr) g_Sc[idx] = 0u;
    for (int idx = gt; idx < NA; idx += nthr) g_keep[idx] = 0;
    int i = gt;
    if (i >= NA) return;
    float ki = key[i];
    int rk = 0;
    for (int j = 0; j < NA; j++) {
        float kj = key[j];
        rk += ((kj > ki) || (kj == ki && j > i)) ? 1 : 0;
    }
    g_order[rk] = i;
    g_rank[i] = rk;
    if (g_mask[i]) atomicAdd(&g_nmask, 1);
}

// ---------------- convex quad intersection area (fp32, bit-faithful) ----------------
// Requires all 32 lanes of the warp converged (uses full-mask shuffles).
__device__ __forceinline__ float quad_inter_area(const float* __restrict__ A, const float* __restrict__ B)
{
    float A0[4], A1[4], B0[4], B1[4];
#pragma unroll
    for (int q = 0; q < 4; q++) {
        A0[q] = A[2 * q]; A1[q] = A[2 * q + 1];
        B0[q] = B[2 * q]; B1[q] = B[2 * q + 1];
    }
    bool inA[4], inB[4];
#pragma unroll
    for (int p = 0; p < 4; p++) {
        bool pos = true, neg = true;
#pragma unroll
        for (int e = 0; e < 4; e++) {
            int e1 = (e + 1) & 3;
            float E0 = fs(A0[e1], A0[e]), E1 = fs(A1[e1], A1[e]);
            float r0 = fs(B0[p], A0[e]), r1 = fs(B1[p], A1[e]);
            float cr = fs(fm(E0, r1), fm(E1, r0));
            pos = pos && (cr >= 0.f);
            neg = neg && (cr <= 0.f);
        }
        inA[p] = pos || neg;
    }
#pragma unroll
    for (int p = 0; p < 4; p++) {
        bool pos = true, neg = true;
#pragma unroll
        for (int e = 0; e < 4; e++) {
            int e1 = (e + 1) & 3;
            float E0 = fs(B0[e1], B0[e]), E1 = fs(B1[e1], B1[e]);
            float r0 = fs(A0[p], B0[e]), r1 = fs(A1[p], B1[e]);
            float cr = fs(fm(E0, r1), fm(E1, r0));
            pos = pos && (cr >= 0.f);
            neg = neg && (cr <= 0.f);
        }
        inB[p] = pos || neg;
    }
    float Px[24], Py[24];
    unsigned val = 0;
#pragma unroll
    for (int p = 0; p < 4; p++) {
        Px[p] = A0[p]; Py[p] = A1[p];
        if (inB[p]) val |= 1u << p;
        Px[4 + p] = B0[p]; Py[4 + p] = B1[p];
        if (inA[p]) val |= 1u << (4 + p);
    }
#pragma unroll
    for (int a = 0; a < 4; a++) {
        int a1 = (a + 1) & 3;
        float rA0 = fs(A0[a1], A0[a]), rA1 = fs(A1[a1], A1[a]);
#pragma unroll
        for (int b = 0; b < 4; b++) {
            int b1 = (b + 1) & 3;
            float rB0 = fs(B0[b1], B0[b]), rB1 = fs(B1[b1], B1[b]);
            float qp0 = fs(B0[b], A0[a]), qp1 = fs(B1[b], A1[a]);
            float den = fs(fm(rA0, rB1), fm(rA1, rB0));
            float dsafe = (fabsf(den) < 1e-9f) ? 1e-9f : den;
            float tt = fd(fs(fm(qp0, rB1), fm(qp1, rB0)), dsafe);
            float uu = fd(fs(fm(qp0, rA1), fm(qp1, rA0)), dsafe);
            bool ok = (fabsf(den) > 1e-9f) && (tt >= 0.f) && (tt <= 1.f) && (uu >= 0.f) && (uu <= 1.f);
            int id = 8 + a * 4 + b;
            Px[id] = fa(A0[a], fm(tt, rA0));
            Py[id] = fa(A1[a], fm(tt, rA1));
            if (ok) val |= 1u << id;
        }
    }
    int n = __popc(val);
    float sx = 0.f, sy = 0.f;
#pragma unroll
    for (int t = 0; t < 24; t++) {
        bool v = (val >> t) & 1u;
        sx = fa(sx, v ? Px[t] : 0.0f);
        sy = fa(sy, v ? Py[t] : 0.0f);
    }
    float inv = (float)max(n, 1);
    float cx = fd(sx, inv), cy = fd(sy, inv);
    float ang[24];
#pragma unroll
    for (int t = 0; t < 24; t++) {
        Px[t] = fs(Px[t], cx); Py[t] = fs(Py[t], cy);   // rel coords
        ang[t] = ((val >> t) & 1u) ? atan2f(Py[t], Px[t]) : 1e9f;
    }
    int rk[24];
#pragma unroll
    for (int t = 0; t < 24; t++) rk[t] = 0;
#pragma unroll
    for (int t = 0; t < 24; t++) {
#pragma unroll
        for (int u = t + 1; u < 24; u++) {
            bool u_first = (ang[u] < ang[t]);
            rk[t] += u_first ? 1 : 0;
            rk[u] += u_first ? 0 : 1;
        }
    }
    float xo0 = 0.f, yo0 = 0.f;
#pragma unroll
    for (int t = 0; t < 24; t++) {
        bool is0 = (rk[t] == 0);
        xo0 = is0 ? Px[t] : xo0;
        yo0 = is0 ? Py[t] : yo0;
    }
    int nmax = n;
#pragma unroll
    for (int o = 16; o; o >>= 1) nmax = max(nmax, __shfl_xor_sync(0xffffffffu, nmax, o));
    float ssum = 0.f;
    float pxc = xo0, pyc = yo0;
    for (int pos = 1; pos < nmax; pos++) {
        float nx = 0.f, ny = 0.f;
#pragma unroll
        for (int t = 0; t < 24; t++) {
            bool h = (rk[t] == pos);
            nx = h ? Px[t] : nx;
            ny = h ? Py[t] : ny;
        }
        if (pos < n) {
            ssum = fa(ssum, fs(fm(pxc, ny), fm(pyc, nx)));
            pxc = nx; pyc = ny;
        }
    }
    ssum = fa(ssum, fs(fm(pxc, yo0), fm(pyc, xo0)));
    float aout = fm(0.5f, fabsf(ssum));
    return (n >= 3) ? aout : 0.f;
}

// ---------------- kernel B1: cheap pair pass; enqueue heavy pairs ----------------
__global__ void k_pairs()
{
    int i = blockIdx.y;
    if (!g_mask[i]) return;                 // uniform across block
    int j = blockIdx.x * blockDim.x + threadIdx.x;
    if (j >= NA) return;

    int nmask = g_nmask;
    int rj = g_rank[j];
    if (rj >= nmask) return;                // column never read by the scan

    float Q[8];
#pragma unroll
    for (int k = 0; k < 8; k++) Q[k] = g_rect[i * 8 + k];
    float p0 = g_y[j], p1 = g_x[j];
    bool pos = true, neg = true;
#pragma unroll
    for (int e = 0; e < 4; e++) {
        int e1 = (e + 1) & 3;
        float E0 = fs(Q[2 * e1], Q[2 * e]), E1 = fs(Q[2 * e1 + 1], Q[2 * e + 1]);
        float r0 = fs(p0, Q[2 * e]), r1 = fs(p1, Q[2 * e + 1]);
        float cr = fs(fm(E0, r1), fm(E1, r0));
        pos = pos && (cr >= 0.f);
        neg = neg && (cr <= 0.f);
    }
    bool bit = pos || neg;
    if (bit) {
        int NWc = (nmask + 31) >> 5;
        int ri = g_rank[i];
        atomicOr(&g_Sc[ri * NWc + (rj >> 5)], 1u << (rj & 31));
        return;
    }
    // AABB gate: disjoint => intersection == 0 exactly => iou < thr
    float im0 = g_ab[i * 4 + 0], iM0 = g_ab[i * 4 + 1];
    float im1 = g_ab[i * 4 + 2], iM1 = g_ab[i * 4 + 3];
    float jm0 = g_ab[j * 4 + 0], jM0 = g_ab[j * 4 + 1];
    float jm1 = g_ab[j * 4 + 2], jM1 = g_ab[j * 4 + 3];
    bool ov = !(iM0 < jm0 || jM0 < im0 || iM1 < jm1 || jM1 < im1);
    if (ov) {
        int idx = atomicAdd(&g_nheavy, 1);
        g_hq[idx] = ((unsigned)i << 16) | (unsigned)j;
    }
}

// ---------------- kernel B2: heavy pairs (live-padded, warp-converged) ----------------
__global__ void __launch_bounds__(128) k_heavy()
{
    int total = g_nheavy;
    if (total == 0) return;
    int nmask = g_nmask;
    int NWc = (nmask + 31) >> 5;
    int gtid = blockIdx.x * blockDim.x + threadIdx.x;
    int nthr = gridDim.x * blockDim.x;
    for (int base = 0; base < total; base += nthr) {
        int idx = base + gtid;
        bool live = idx < total;
        unsigned pk = g_hq[live ? idx : 0];
        int i = pk >> 16, j = pk & 0xFFFF;
        float inter = quad_inter_area(&g_cor[i * 8], &g_cor[j * 8]);
        float iou = fd(inter, fa(fs(fa(g_a5[i], g_a5[j]), inter), 1e-9f));
        if (live && iou >= 0.2f) {
            int ri = g_rank[i], rj = g_rank[j];
            atomicOr(&g_Sc[ri * NWc + (rj >> 5)], 1u << (rj & 31));
        }
    }
}

// ---------------- kernel C: block-parallel sequential NMS + outputs ----------------
__global__ void __launch_bounds__(1024) k_nms(float* __restrict__ dout)
{
    extern __shared__ unsigned int sS[];        // nrows*NWc words (rank rows) + nrows ints (order)
    __shared__ unsigned int sSup[64];
    __shared__ unsigned int sAct;
    __shared__ int sc0, sc1;
    int tid = threadIdx.x;

    int nmask = g_nmask;
    int nchunks = (nmask + 31) >> 5;
    int NWc = nchunks;
    int nrows = nchunks << 5;
    int* sOrd = (int*)(sS + nrows * NWc);

    for (int idx = tid; idx < nrows * NWc; idx += blockDim.x) sS[idx] = g_Sc[idx];
    for (int idx = tid; idx < nrows; idx += blockDim.x) sOrd[idx] = g_order[idx];
    if (tid < 64) {
        // sup init in rank space: bit r set iff r >= nmask
        int base = tid << 5;
        unsigned wv;
        if (base + 32 <= nmask) wv = 0u;
        else if (base >= nmask) wv = 0xFFFFFFFFu;
        else wv = 0xFFFFFFFFu << (nmask - base);
        sSup[tid] = wv;
    }
    if (tid == 0) { sc0 = 0; sc1 = 0; }
    __syncthreads();

    int orTotal = NWc << 5;   // 32 rows x NWc words
    for (int k = 0; k < nmask; k += 32) {
        int c = k >> 5;
        if (tid < 32) {
            int lane = tid;
            unsigned sup32 = sSup[c];                  // broadcast LDS
            unsigned mw[32];
#pragma unroll
            for (int b = 0; b < 32; b++) mw[b] = sS[(k + b) * NWc + c];
            unsigned chk = 0;
#pragma unroll
            for (int b = 0; b < 32; b++) chk ^= mw[b];
            unsigned s32 = sup32;
            asm volatile("" : "+r"(s32) : "r"(chk));
            // serial closure over 32 ranks -- pure register ALU chain
            unsigned act = 0;
#pragma unroll
            for (int b = 0; b < 32; b++) {
                unsigned m = (unsigned)(((int)(s32 << (31 - b))) >> 31);  // all-ones if suppressed
                act |= (~m) & (1u << b);
                s32 |= mw[b] & ~m;
            }
            if ((act >> lane) & 1u) g_keep[sOrd[k + lane]] = 1;
            if (lane == 0) sAct = act;
        }
        __syncthreads();
        unsigned act = sAct;
        // block-parallel OR of active rows into sSup
        for (int idx = tid; idx < orTotal; idx += blockDim.x) {
            int b = idx / NWc;
            int w = idx - b * NWc;
            if ((act >> b) & 1u)
                atomicOr(&sSup[w], sS[(k + b) * NWc + w]);
        }
        __syncthreads();
    }

    // class counts
    int l0 = 0, l1 = 0;
    for (int i = tid; i < NA; i += blockDim.x) {
        if (g_keep[i]) {
            float mx = fmaxf(g_cls0[i], g_cls1[i]);
            if (g_cls0[i] == mx) l0++;
            if (g_cls1[i] == mx) l1++;
        }
    }
    atomicAdd(&sc0, l0);
    atomicAdd(&sc1, l1);
    __syncthreads();
    if (tid == 0) { dout[0] = (float)sc0; dout[1] = (float)sc1; }

    // outputs (fused former k_out)
    for (int t = tid; t < NA; t += blockDim.x) {
        bool kp = g_keep[t] != 0;
        float mx = fmaxf(g_cls0[t], g_cls1[t]);
        bool m0 = kp && (g_cls0[t] == mx);
        bool m1 = kp && (g_cls1[t] == mx);
        float x = g_x[t], y = g_y[t];
        float* res = dout + 2;                 // (2, NA, 2)
        res[0 * NA * 2 + t * 2 + 0] = m0 ? x : 0.f;
        res[0 * NA * 2 + t * 2 + 1] = m0 ? y : 0.f;
        res[1 * NA * 2 + t * 2 + 0] = m1 ? x : 0.f;
        res[1 * NA * 2 + t * 2 + 1] = m1 ? y : 0.f;
        float* ro = dout + 2 + 2 * NA * 2;     // (NA, 8)
        float kf = kp ? 1.f : 0.f;
#pragma unroll
        for (int k = 0; k < 8; k++)
            ro[t * 8 + k] = fm(g_rect[t * 8 + k], kf);
    }
}

// ---------------- launcher ----------------
extern "C" void kernel_launch(void* const* d_in, const int* in_sizes, int n_in,
                              void* d_out, int out_size)
{
    const float* out3 = (const float*)d_in[0];
    const float* out4 = (const float*)d_in[1];
    const float* out5 = (const float*)d_in[2];
    const float* o13  = (const float*)d_in[3];
    const float* o14  = (const float*)d_in[4];
    const float* o15  = (const float*)d_in[5];
    const float* of3  = (const float*)d_in[6];
    const float* of4  = (const float*)d_in[7];
    const float* of5  = (const float*)d_in[8];
    float* dout = (float*)d_out;

    k_geom<<<(NA + 127) / 128, 128>>>(out3, out4, out5, o13, o14, o15, of3, of4, of5);
    k_rank<<<(NA + 255) / 256, 256>>>();
    dim3 gB((NA + 255) / 256, NA);
    k_pairs<<<gB, 256>>>();
    k_heavy<<<296, 128>>>();   // live-padded grid-stride over heavy queue
    size_t sh = (size_t)NA * NW * sizeof(unsigned int) + (size_t)NA * sizeof(int);  // worst case
    cudaFuncSetAttribute(k_nms, cudaFuncAttributeMaxDynamicSharedMemorySize, (int)sh);
    k_nms<<<1, 1024, sh>>>(dout);
}